// round 14
// baseline (speedup 1.0000x reference)
#include <cuda_runtime.h>
#include <cuda_fp16.h>
#include <mma.h>
#include <cstdint>

using namespace nvcuda;

#define N_NODES_MAX 50000
#define N_EDGES_MAX 1600000
#define IN_DIM 128
#define QKV_DIM 128   // OUT_DIM * N_HEADS = 16*8

// ---------------- device scratch (allocation-free rule: __device__ globals) ----
__device__ float  g_Q [(size_t)N_NODES_MAX * QKV_DIM];
__device__ __half g_Kh[(size_t)N_NODES_MAX * QKV_DIM];
__device__ __half g_Vh[(size_t)N_NODES_MAX * QKV_DIM];
__device__ __half g_W16[3 * 128 * 128];   // [mat][k][n] row-major fp16
__device__ int    g_off[N_NODES_MAX + 1];
__device__ int    g_cur[N_NODES_MAX];
__device__ int    g_srcs[N_EDGES_MAX];
__device__ int    g_bsum[64];

__device__ __forceinline__ unsigned int h2u(__half2 h) {
    return *reinterpret_cast<unsigned int*>(&h);
}

// ---------------- prep: W fp32 -> fp16 (same [k][n] row-major layout) -----------
__global__ void wprep_kernel(const float* __restrict__ Wq,
                             const float* __restrict__ Wk,
                             const float* __restrict__ Wv) {
    const float* W = (blockIdx.x == 0) ? Wq : (blockIdx.x == 1) ? Wk : Wv;
    __half* O = g_W16 + blockIdx.x * 16384;
    for (int i = threadIdx.x * 4; i < 16384; i += blockDim.x * 4) {
        float4 f = *(const float4*)(W + i);
        uint2 u;
        u.x = h2u(__floats2half2_rn(f.x, f.y));
        u.y = h2u(__floats2half2_rn(f.z, f.w));
        *(uint2*)(O + i) = u;
    }
}

// ---------------- kernel 1: fused QKV projection (smem-staged wmma) -------------
// Block: 64 nodes, ALL THREE matrices. A staged once from fp32 h (inline fp16
// convert); per mat: stage B, mma, epilogue (B smem reused as fp32 staging).
// Warp layout: 8 warps = 4 row-groups (16 nodes) x 2 col-groups (64 cols);
// each warp: 4 acc fragments.
#define LDP 136                         // padded smem leading dim (halfs)
#define SMA_BYTES (64 * LDP * 2)        // 17408
#define SMB_BYTES (128 * LDP * 2)       // 34816
#define SM_TOTAL  (SMA_BYTES + SMB_BYTES)  // 52224

__global__ void __launch_bounds__(256)
wmma_qkv_kernel(const float* __restrict__ h,
                const float* __restrict__ bq,
                const float* __restrict__ bk,
                const float* __restrict__ bv,
                int nN)
{
    extern __shared__ char sm[];
    __half* smA = (__half*)sm;
    __half* smB = (__half*)(sm + SMA_BYTES);

    const int t    = threadIdx.x;
    const int warp = t >> 5;
    const int lane = t & 31;
    const int m0   = blockIdx.x * 64;
    const int wr   = warp & 3;          // 16-node row group
    const int wc   = warp >> 2;         // 64-col group
    const int node0 = m0 + wr * 16;

    // stage A: 64 rows x 128 cols, fp32 -> fp16, guarded on last tile
#pragma unroll
    for (int i = 0; i < 8; i++) {
        int g   = t + i * 256;          // float4-chunk id, 0..2047
        int row = g >> 5;               // 32 chunks per row
        int ch  = g & 31;
        float4 f = make_float4(0.f, 0.f, 0.f, 0.f);
        if (m0 + row < nN)
            f = *(const float4*)(h + (size_t)(m0 + row) * IN_DIM + ch * 4);
        uint2 u;
        u.x = h2u(__floats2half2_rn(f.x, f.y));
        u.y = h2u(__floats2half2_rn(f.z, f.w));
        *(uint2*)(smA + row * LDP + ch * 4) = u;
    }

#pragma unroll
    for (int mat = 0; mat < 3; mat++) {
        // stage B: 128x128 halfs (uint4 per thread x8)
#pragma unroll
        for (int i = 0; i < 8; i++) {
            int g   = t + i * 256;
            int row = g >> 4;
            int ch  = g & 15;
            uint4 u = *(const uint4*)(g_W16 + mat * 16384 + row * 128 + ch * 8);
            *(uint4*)(smB + row * LDP + ch * 8) = u;
        }
        __syncthreads();

        wmma::fragment<wmma::accumulator, 16, 16, 16, float> acc[4];
#pragma unroll
        for (int j = 0; j < 4; j++) wmma::fill_fragment(acc[j], 0.f);

#pragma unroll
        for (int k = 0; k < 128; k += 16) {
            wmma::fragment<wmma::matrix_a, 16, 16, 16, __half, wmma::row_major> a;
            wmma::load_matrix_sync(a, smA + wr * 16 * LDP + k, LDP);
#pragma unroll
            for (int j = 0; j < 4; j++) {
                wmma::fragment<wmma::matrix_b, 16, 16, 16, __half, wmma::row_major> b;
                wmma::load_matrix_sync(b, smB + k * LDP + wc * 64 + j * 16, LDP);
                wmma::mma_sync(acc[j], a, b, acc[j]);
            }
        }
        __syncthreads();   // B reads complete everywhere; reuse B smem as staging

        float* stg = (float*)smB + warp * (16 * 64);   // 4 KB per warp, 32 KB total
#pragma unroll
        for (int j = 0; j < 4; j++)
            wmma::store_matrix_sync(stg + j * 16, acc[j], 64, wmma::mem_row_major);
        __syncwarp();

        // writeout: warp covers rows node0..node0+15, cols wc*64..wc*64+63.
        // lane owns 2 cols.
        const float* bias = (mat == 0) ? bq : (mat == 1) ? bk : bv;
        int cg = wc * 64 + lane * 2;
        float2 bb = *(const float2*)(bias + cg);
        if (mat == 0) {
#pragma unroll
            for (int r = 0; r < 16; r++) {
                int node = node0 + r;
                if (node >= nN) break;
                float2 v = *(float2*)&stg[r * 64 + lane * 2];
                v.x += bb.x; v.y += bb.y;
                *(float2*)(g_Q + (size_t)node * QKV_DIM + cg) = v;
            }
        } else {
            __half* P = (mat == 1) ? g_Kh : g_Vh;
#pragma unroll
            for (int r = 0; r < 16; r++) {
                int node = node0 + r;
                if (node >= nN) break;
                float2 v = *(float2*)&stg[r * 64 + lane * 2];
                unsigned int u = h2u(__floats2half2_rn(v.x + bb.x, v.y + bb.y));
                *(unsigned int*)(P + (size_t)node * QKV_DIM + cg) = u;
            }
        }
        __syncthreads();   // staging done before restaging B for next mat
    }
}

// ---------------- CSR build kernels ---------------------------------------------
__global__ void zero_off_kernel(int n) {
    int i = blockIdx.x * blockDim.x + threadIdx.x;
    if (i <= n) g_off[i] = 0;
}

__global__ void hist_kernel(const int* __restrict__ dst, int nE) {
    int e = blockIdx.x * blockDim.x + threadIdx.x;
    if (e < nE) atomicAdd(&g_off[dst[e] + 1], 1);
}

__global__ void __launch_bounds__(1024)
block_scan_kernel(int n) {
    __shared__ int wsum[32];
    int t    = threadIdx.x;
    int lane = t & 31;
    int wid  = t >> 5;
    int i = blockIdx.x * 1024 + t + 1;
    int x = (i <= n) ? g_off[i] : 0;
#pragma unroll
    for (int d = 1; d < 32; d <<= 1) {
        int y = __shfl_up_sync(0xffffffffu, x, d);
        if (lane >= d) x += y;
    }
    if (lane == 31) wsum[wid] = x;
    __syncthreads();
    if (wid == 0) {
        int s = wsum[lane];
#pragma unroll
        for (int d = 1; d < 32; d <<= 1) {
            int y = __shfl_up_sync(0xffffffffu, s, d);
            if (lane >= d) s += y;
        }
        wsum[lane] = s;
    }
    __syncthreads();
    if (wid > 0) x += wsum[wid - 1];
    if (i <= n) g_off[i] = x;
    if (t == 1023) g_bsum[blockIdx.x] = x;
}

__global__ void __launch_bounds__(1024)
scan_add_kernel(int n, int nb) {
    __shared__ int part[64];
    __shared__ int s_add;
    int t = threadIdx.x;
    if (t < 64) part[t] = (t < nb && t < (int)blockIdx.x) ? g_bsum[t] : 0;
    __syncthreads();
    if (t < 32) {
        int s = part[t] + part[t + 32];
#pragma unroll
        for (int d = 16; d > 0; d >>= 1) s += __shfl_down_sync(0xffffffffu, s, d);
        if (t == 0) s_add = s;
    }
    __syncthreads();
    int add = s_add;
    int i = blockIdx.x * 1024 + t + 1;
    if (i <= n) {
        int v = g_off[i] + add;
        g_off[i] = v;
        if (i < n) g_cur[i] = v;
    }
    if (blockIdx.x == 0 && t == 0) g_cur[0] = 0;
}

__global__ void scatter_kernel(const int* __restrict__ src, const int* __restrict__ dst, int nE) {
    int e = blockIdx.x * blockDim.x + threadIdx.x;
    if (e < nE) {
        int d = dst[e];
        int p = atomicAdd(&g_cur[d], 1);
        g_srcs[p] = src[e];
    }
}

// ---------------- consume: per-node pull attention (one warp per dst node) ------
__device__ __forceinline__ float dot4_h(uint2 u, float4 q) {
    float2 a = __half22float2(*reinterpret_cast<__half2*>(&u.x));
    float2 b = __half22float2(*reinterpret_cast<__half2*>(&u.y));
    return a.x * q.x + a.y * q.y + b.x * q.z + b.y * q.w;
}
__device__ __forceinline__ void acc4_h(uint2 u, float s, float4& acc) {
    float2 a = __half22float2(*reinterpret_cast<__half2*>(&u.x));
    float2 b = __half22float2(*reinterpret_cast<__half2*>(&u.y));
    acc.x = fmaf(a.x, s, acc.x);
    acc.y = fmaf(a.y, s, acc.y);
    acc.z = fmaf(b.x, s, acc.z);
    acc.w = fmaf(b.y, s, acc.w);
}

__global__ void __launch_bounds__(256)
consume_kernel(float* __restrict__ out, int nN) {
    int w    = (blockIdx.x * blockDim.x + threadIdx.x) >> 5;
    int lane = threadIdx.x & 31;
    if (w >= nN) return;

    const float4* Q4 = (const float4*)g_Q;
    const uint2*  K2 = (const uint2*)g_Kh;
    const uint2*  V2 = (const uint2*)g_Vh;

    int beg = g_off[w];
    int end = g_off[w + 1];

    float4 q   = Q4[(size_t)w * 32 + lane];
    float4 acc = make_float4(0.f, 0.f, 0.f, 0.f);
    float  z   = 0.f;

    int j = beg;
    for (; j + 3 < end; j += 4) {
        int s0 = g_srcs[j];
        int s1 = g_srcs[j + 1];
        int s2 = g_srcs[j + 2];
        int s3 = g_srcs[j + 3];
        uint2 k0 = K2[(size_t)s0 * 32 + lane];
        uint2 k1 = K2[(size_t)s1 * 32 + lane];
        uint2 k2 = K2[(size_t)s2 * 32 + lane];
        uint2 k3 = K2[(size_t)s3 * 32 + lane];
        uint2 v0 = V2[(size_t)s0 * 32 + lane];
        uint2 v1 = V2[(size_t)s1 * 32 + lane];
        uint2 v2 = V2[(size_t)s2 * 32 + lane];
        uint2 v3 = V2[(size_t)s3 * 32 + lane];

        float p0 = dot4_h(k0, q);
        float p1 = dot4_h(k1, q);
        float p2 = dot4_h(k2, q);
        float p3 = dot4_h(k3, q);
        p0 += __shfl_xor_sync(0xffffffffu, p0, 1);
        p0 += __shfl_xor_sync(0xffffffffu, p0, 2);
        p1 += __shfl_xor_sync(0xffffffffu, p1, 1);
        p1 += __shfl_xor_sync(0xffffffffu, p1, 2);
        p2 += __shfl_xor_sync(0xffffffffu, p2, 1);
        p2 += __shfl_xor_sync(0xffffffffu, p2, 2);
        p3 += __shfl_xor_sync(0xffffffffu, p3, 1);
        p3 += __shfl_xor_sync(0xffffffffu, p3, 2);

        float sc0 = __expf(fminf(fmaxf(p0 * 0.25f, -5.f), 5.f));
        float sc1 = __expf(fminf(fmaxf(p1 * 0.25f, -5.f), 5.f));
        float sc2 = __expf(fminf(fmaxf(p2 * 0.25f, -5.f), 5.f));
        float sc3 = __expf(fminf(fmaxf(p3 * 0.25f, -5.f), 5.f));

        acc4_h(v0, sc0, acc);
        acc4_h(v1, sc1, acc);
        acc4_h(v2, sc2, acc);
        acc4_h(v3, sc3, acc);
        z += (sc0 + sc1) + (sc2 + sc3);
    }
    for (; j < end; j++) {
        int s0 = g_srcs[j];
        uint2 k0 = K2[(size_t)s0 * 32 + lane];
        uint2 v0 = V2[(size_t)s0 * 32 + lane];
        float p0 = dot4_h(k0, q);
        p0 += __shfl_xor_sync(0xffffffffu, p0, 1);
        p0 += __shfl_xor_sync(0xffffffffu, p0, 2);
        float sc0 = __expf(fminf(fmaxf(p0 * 0.25f, -5.f), 5.f));
        acc4_h(v0, sc0, acc);
        z += sc0;
    }

    float inv = 1.f / (z + 1e-6f);
    float4 o = make_float4(acc.x * inv, acc.y * inv, acc.z * inv, acc.w * inv);
    *(float4*)(out + (size_t)w * QKV_DIM + lane * 4) = o;
}

// ---------------- launch ---------------------------------------------------------
extern "C" void kernel_launch(void* const* d_in, const int* in_sizes, int n_in,
                              void* d_out, int out_size)
{
    const float* h  = (const float*)d_in[0];
    const float* Wq = (const float*)d_in[1];
    const float* bq = (const float*)d_in[2];
    const float* Wk = (const float*)d_in[3];
    const float* bk = (const float*)d_in[4];
    const float* Wv = (const float*)d_in[5];
    const float* bv = (const float*)d_in[6];
    const int*   src = (const int*)d_in[7];
    const int*   dst = (const int*)d_in[8];

    int nN = in_sizes[0] / IN_DIM;
    int nE = in_sizes[7];
    if (nN > N_NODES_MAX) nN = N_NODES_MAX;
    if (nE > N_EDGES_MAX) nE = N_EDGES_MAX;

    float* out = (float*)d_out;
    int nb = (nN + 1023) / 1024;

    static bool attr_done = false;
    if (!attr_done) {
        cudaFuncSetAttribute(wmma_qkv_kernel,
                             cudaFuncAttributeMaxDynamicSharedMemorySize, SM_TOTAL);
        attr_done = true;
    }

    static cudaStream_t s2 = nullptr;
    static cudaEvent_t  evF = nullptr, evJ = nullptr;
    if (!s2) {
        if (cudaStreamCreateWithFlags(&s2, cudaStreamNonBlocking) != cudaSuccess) s2 = nullptr;
        if (s2) {
            if (cudaEventCreateWithFlags(&evF, cudaEventDisableTiming) != cudaSuccess) evF = nullptr;
            if (cudaEventCreateWithFlags(&evJ, cudaEventDisableTiming) != cudaSuccess) evJ = nullptr;
        }
    }
    bool fork = (s2 && evF && evJ);

    int ggrid = (nN + 63) / 64;

    if (fork) {
        cudaEventRecord(evF, 0);
        cudaStreamWaitEvent(s2, evF, 0);

        zero_off_kernel<<<(nN + 1 + 255) / 256, 256, 0, s2>>>(nN);
        hist_kernel<<<(nE + 255) / 256, 256, 0, s2>>>(dst, nE);
        block_scan_kernel<<<nb, 1024, 0, s2>>>(nN);
        scan_add_kernel<<<nb, 1024, 0, s2>>>(nN, nb);
        scatter_kernel<<<(nE + 255) / 256, 256, 0, s2>>>(src, dst, nE);
        cudaEventRecord(evJ, s2);

        wprep_kernel<<<3, 256>>>(Wq, Wk, Wv);
        wmma_qkv_kernel<<<ggrid, 256, SM_TOTAL>>>(h, bq, bk, bv, nN);

        cudaStreamWaitEvent(0, evJ, 0);
    } else {
        zero_off_kernel<<<(nN + 1 + 255) / 256, 256>>>(nN);
        wprep_kernel<<<3, 256>>>(Wq, Wk, Wv);
        wmma_qkv_kernel<<<ggrid, 256, SM_TOTAL>>>(h, bq, bk, bv, nN);
        hist_kernel<<<(nE + 255) / 256, 256>>>(dst, nE);
        block_scan_kernel<<<nb, 1024>>>(nN);
        scan_add_kernel<<<nb, 1024>>>(nN, nb);
        scatter_kernel<<<(nE + 255) / 256, 256>>>(src, dst, nE);
    }

    int nBlocks = (nN + 7) / 8;
    consume_kernel<<<nBlocks, 256>>>(out, nN);

    (void)n_in; (void)out_size;
}

// round 15
// speedup vs baseline: 1.0030x; 1.0030x over previous
#include <cuda_runtime.h>
#include <cuda_fp16.h>
#include <mma.h>
#include <cstdint>

using namespace nvcuda;

#define N_NODES_MAX 50000
#define N_EDGES_MAX 1600000
#define IN_DIM 128
#define QKV_DIM 128   // OUT_DIM * N_HEADS = 16*8

// ---------------- device scratch (allocation-free rule: __device__ globals) ----
__device__ float  g_Q [(size_t)N_NODES_MAX * QKV_DIM];
__device__ __half g_Kh[(size_t)N_NODES_MAX * QKV_DIM];
__device__ __half g_Vh[(size_t)N_NODES_MAX * QKV_DIM];
__device__ __half g_W16[3 * 128 * 128];   // [mat][k][n] row-major fp16
__device__ int    g_off[N_NODES_MAX + 1];
__device__ int    g_cur[N_NODES_MAX];
__device__ int    g_srcs[N_EDGES_MAX];
__device__ int    g_bsum[64];

__device__ __forceinline__ unsigned int h2u(__half2 h) {
    return *reinterpret_cast<unsigned int*>(&h);
}

// ---------------- prep: W fp32 -> fp16 (same [k][n] row-major layout) -----------
__global__ void wprep_kernel(const float* __restrict__ Wq,
                             const float* __restrict__ Wk,
                             const float* __restrict__ Wv) {
    const float* W = (blockIdx.x == 0) ? Wq : (blockIdx.x == 1) ? Wk : Wv;
    __half* O = g_W16 + blockIdx.x * 16384;
    for (int i = threadIdx.x * 4; i < 16384; i += blockDim.x * 4) {
        float4 f = *(const float4*)(W + i);
        uint2 u;
        u.x = h2u(__floats2half2_rn(f.x, f.y));
        u.y = h2u(__floats2half2_rn(f.z, f.w));
        *(uint2*)(O + i) = u;
    }
}

// ---------------- kernel 1: fused QKV projection (smem-staged wmma) -------------
// Block: 64 nodes, ALL THREE matrices. A staged once from fp32 h (inline fp16
// convert); per mat: stage B, mma, epilogue (B smem reused as fp32 staging).
// Warp layout: 8 warps = 4 row-groups (16 nodes) x 2 col-groups (64 cols);
// each warp: 4 acc fragments.
#define LDP 136                         // padded smem leading dim (halfs)
#define SMA_BYTES (64 * LDP * 2)        // 17408
#define SMB_BYTES (128 * LDP * 2)       // 34816
#define SM_TOTAL  (SMA_BYTES + SMB_BYTES)  // 52224

__global__ void __launch_bounds__(256)
wmma_qkv_kernel(const float* __restrict__ h,
                const float* __restrict__ bq,
                const float* __restrict__ bk,
                const float* __restrict__ bv,
                int nN)
{
    extern __shared__ char sm[];
    __half* smA = (__half*)sm;
    __half* smB = (__half*)(sm + SMA_BYTES);

    const int t    = threadIdx.x;
    const int warp = t >> 5;
    const int lane = t & 31;
    const int m0   = blockIdx.x * 64;
    const int wr   = warp & 3;          // 16-node row group
    const int wc   = warp >> 2;         // 64-col group
    const int node0 = m0 + wr * 16;

    // stage A: 64 rows x 128 cols, fp32 -> fp16, guarded on last tile
#pragma unroll
    for (int i = 0; i < 8; i++) {
        int g   = t + i * 256;          // float4-chunk id, 0..2047
        int row = g >> 5;               // 32 chunks per row
        int ch  = g & 31;
        float4 f = make_float4(0.f, 0.f, 0.f, 0.f);
        if (m0 + row < nN)
            f = *(const float4*)(h + (size_t)(m0 + row) * IN_DIM + ch * 4);
        uint2 u;
        u.x = h2u(__floats2half2_rn(f.x, f.y));
        u.y = h2u(__floats2half2_rn(f.z, f.w));
        *(uint2*)(smA + row * LDP + ch * 4) = u;
    }

#pragma unroll
    for (int mat = 0; mat < 3; mat++) {
        // stage B: 128x128 halfs (uint4 per thread x8)
#pragma unroll
        for (int i = 0; i < 8; i++) {
            int g   = t + i * 256;
            int row = g >> 4;
            int ch  = g & 15;
            uint4 u = *(const uint4*)(g_W16 + mat * 16384 + row * 128 + ch * 8);
            *(uint4*)(smB + row * LDP + ch * 8) = u;
        }
        __syncthreads();

        wmma::fragment<wmma::accumulator, 16, 16, 16, float> acc[4];
#pragma unroll
        for (int j = 0; j < 4; j++) wmma::fill_fragment(acc[j], 0.f);

#pragma unroll
        for (int k = 0; k < 128; k += 16) {
            wmma::fragment<wmma::matrix_a, 16, 16, 16, __half, wmma::row_major> a;
            wmma::load_matrix_sync(a, smA + wr * 16 * LDP + k, LDP);
#pragma unroll
            for (int j = 0; j < 4; j++) {
                wmma::fragment<wmma::matrix_b, 16, 16, 16, __half, wmma::row_major> b;
                wmma::load_matrix_sync(b, smB + k * LDP + wc * 64 + j * 16, LDP);
                wmma::mma_sync(acc[j], a, b, acc[j]);
            }
        }
        __syncthreads();   // B reads complete everywhere; reuse B smem as staging

        float* stg = (float*)smB + warp * (16 * 64);   // 4 KB per warp, 32 KB total
#pragma unroll
        for (int j = 0; j < 4; j++)
            wmma::store_matrix_sync(stg + j * 16, acc[j], 64, wmma::mem_row_major);
        __syncwarp();

        // writeout: warp covers rows node0..node0+15, cols wc*64..wc*64+63.
        // lane owns 2 cols.
        const float* bias = (mat == 0) ? bq : (mat == 1) ? bk : bv;
        int cg = wc * 64 + lane * 2;
        float2 bb = *(const float2*)(bias + cg);
        if (mat == 0) {
#pragma unroll
            for (int r = 0; r < 16; r++) {
                int node = node0 + r;
                if (node >= nN) break;
                float2 v = *(float2*)&stg[r * 64 + lane * 2];
                v.x += bb.x; v.y += bb.y;
                *(float2*)(g_Q + (size_t)node * QKV_DIM + cg) = v;
            }
        } else {
            __half* P = (mat == 1) ? g_Kh : g_Vh;
#pragma unroll
            for (int r = 0; r < 16; r++) {
                int node = node0 + r;
                if (node >= nN) break;
                float2 v = *(float2*)&stg[r * 64 + lane * 2];
                unsigned int u = h2u(__floats2half2_rn(v.x + bb.x, v.y + bb.y));
                *(unsigned int*)(P + (size_t)node * QKV_DIM + cg) = u;
            }
        }
        __syncthreads();   // staging done before restaging B for next mat
    }
}

// ---------------- CSR build kernels ---------------------------------------------
__global__ void zero_off_kernel(int n) {
    int i = blockIdx.x * blockDim.x + threadIdx.x;
    if (i <= n) g_off[i] = 0;
}

__global__ void hist_kernel(const int* __restrict__ dst, int nE) {
    int e = blockIdx.x * blockDim.x + threadIdx.x;
    if (e < nE) atomicAdd(&g_off[dst[e] + 1], 1);
}

__global__ void __launch_bounds__(1024)
block_scan_kernel(int n) {
    __shared__ int wsum[32];
    int t    = threadIdx.x;
    int lane = t & 31;
    int wid  = t >> 5;
    int i = blockIdx.x * 1024 + t + 1;
    int x = (i <= n) ? g_off[i] : 0;
#pragma unroll
    for (int d = 1; d < 32; d <<= 1) {
        int y = __shfl_up_sync(0xffffffffu, x, d);
        if (lane >= d) x += y;
    }
    if (lane == 31) wsum[wid] = x;
    __syncthreads();
    if (wid == 0) {
        int s = wsum[lane];
#pragma unroll
        for (int d = 1; d < 32; d <<= 1) {
            int y = __shfl_up_sync(0xffffffffu, s, d);
            if (lane >= d) s += y;
        }
        wsum[lane] = s;
    }
    __syncthreads();
    if (wid > 0) x += wsum[wid - 1];
    if (i <= n) g_off[i] = x;
    if (t == 1023) g_bsum[blockIdx.x] = x;
}

__global__ void __launch_bounds__(1024)
scan_add_kernel(int n, int nb) {
    __shared__ int part[64];
    __shared__ int s_add;
    int t = threadIdx.x;
    if (t < 64) part[t] = (t < nb && t < (int)blockIdx.x) ? g_bsum[t] : 0;
    __syncthreads();
    if (t < 32) {
        int s = part[t] + part[t + 32];
#pragma unroll
        for (int d = 16; d > 0; d >>= 1) s += __shfl_down_sync(0xffffffffu, s, d);
        if (t == 0) s_add = s;
    }
    __syncthreads();
    int add = s_add;
    int i = blockIdx.x * 1024 + t + 1;
    if (i <= n) {
        int v = g_off[i] + add;
        g_off[i] = v;
        if (i < n) g_cur[i] = v;
    }
    if (blockIdx.x == 0 && t == 0) g_cur[0] = 0;
}

__global__ void scatter_kernel(const int* __restrict__ src, const int* __restrict__ dst, int nE) {
    int e = blockIdx.x * blockDim.x + threadIdx.x;
    if (e < nE) {
        int d = dst[e];
        int p = atomicAdd(&g_cur[d], 1);
        g_srcs[p] = src[e];
    }
}

// ---------------- consume: per-node pull attention (one warp per dst node) ------
__device__ __forceinline__ float dot4_h(uint2 u, float4 q) {
    float2 a = __half22float2(*reinterpret_cast<__half2*>(&u.x));
    float2 b = __half22float2(*reinterpret_cast<__half2*>(&u.y));
    return a.x * q.x + a.y * q.y + b.x * q.z + b.y * q.w;
}
__device__ __forceinline__ void acc4_h(uint2 u, float s, float4& acc) {
    float2 a = __half22float2(*reinterpret_cast<__half2*>(&u.x));
    float2 b = __half22float2(*reinterpret_cast<__half2*>(&u.y));
    acc.x = fmaf(a.x, s, acc.x);
    acc.y = fmaf(a.y, s, acc.y);
    acc.z = fmaf(b.x, s, acc.z);
    acc.w = fmaf(b.y, s, acc.w);
}

__global__ void __launch_bounds__(256)
consume_kernel(float* __restrict__ out, int nN) {
    int w    = (blockIdx.x * blockDim.x + threadIdx.x) >> 5;
    int lane = threadIdx.x & 31;
    if (w >= nN) return;

    const float4* Q4 = (const float4*)g_Q;
    const uint2*  K2 = (const uint2*)g_Kh;
    const uint2*  V2 = (const uint2*)g_Vh;

    int beg = g_off[w];
    int end = g_off[w + 1];

    float4 q   = Q4[(size_t)w * 32 + lane];
    float4 acc = make_float4(0.f, 0.f, 0.f, 0.f);
    float  z   = 0.f;

    int j = beg;
    for (; j + 3 < end; j += 4) {
        int s0 = g_srcs[j];
        int s1 = g_srcs[j + 1];
        int s2 = g_srcs[j + 2];
        int s3 = g_srcs[j + 3];
        uint2 k0 = K2[(size_t)s0 * 32 + lane];
        uint2 k1 = K2[(size_t)s1 * 32 + lane];
        uint2 k2 = K2[(size_t)s2 * 32 + lane];
        uint2 k3 = K2[(size_t)s3 * 32 + lane];
        uint2 v0 = V2[(size_t)s0 * 32 + lane];
        uint2 v1 = V2[(size_t)s1 * 32 + lane];
        uint2 v2 = V2[(size_t)s2 * 32 + lane];
        uint2 v3 = V2[(size_t)s3 * 32 + lane];

        float p0 = dot4_h(k0, q);
        float p1 = dot4_h(k1, q);
        float p2 = dot4_h(k2, q);
        float p3 = dot4_h(k3, q);
        p0 += __shfl_xor_sync(0xffffffffu, p0, 1);
        p0 += __shfl_xor_sync(0xffffffffu, p0, 2);
        p1 += __shfl_xor_sync(0xffffffffu, p1, 1);
        p1 += __shfl_xor_sync(0xffffffffu, p1, 2);
        p2 += __shfl_xor_sync(0xffffffffu, p2, 1);
        p2 += __shfl_xor_sync(0xffffffffu, p2, 2);
        p3 += __shfl_xor_sync(0xffffffffu, p3, 1);
        p3 += __shfl_xor_sync(0xffffffffu, p3, 2);

        float sc0 = __expf(fminf(fmaxf(p0 * 0.25f, -5.f), 5.f));
        float sc1 = __expf(fminf(fmaxf(p1 * 0.25f, -5.f), 5.f));
        float sc2 = __expf(fminf(fmaxf(p2 * 0.25f, -5.f), 5.f));
        float sc3 = __expf(fminf(fmaxf(p3 * 0.25f, -5.f), 5.f));

        acc4_h(v0, sc0, acc);
        acc4_h(v1, sc1, acc);
        acc4_h(v2, sc2, acc);
        acc4_h(v3, sc3, acc);
        z += (sc0 + sc1) + (sc2 + sc3);
    }
    for (; j < end; j++) {
        int s0 = g_srcs[j];
        uint2 k0 = K2[(size_t)s0 * 32 + lane];
        uint2 v0 = V2[(size_t)s0 * 32 + lane];
        float p0 = dot4_h(k0, q);
        p0 += __shfl_xor_sync(0xffffffffu, p0, 1);
        p0 += __shfl_xor_sync(0xffffffffu, p0, 2);
        float sc0 = __expf(fminf(fmaxf(p0 * 0.25f, -5.f), 5.f));
        acc4_h(v0, sc0, acc);
        z += sc0;
    }

    float inv = 1.f / (z + 1e-6f);
    float4 o = make_float4(acc.x * inv, acc.y * inv, acc.z * inv, acc.w * inv);
    *(float4*)(out + (size_t)w * QKV_DIM + lane * 4) = o;
}

// ---------------- launch ---------------------------------------------------------
extern "C" void kernel_launch(void* const* d_in, const int* in_sizes, int n_in,
                              void* d_out, int out_size)
{
    const float* h  = (const float*)d_in[0];
    const float* Wq = (const float*)d_in[1];
    const float* bq = (const float*)d_in[2];
    const float* Wk = (const float*)d_in[3];
    const float* bk = (const float*)d_in[4];
    const float* Wv = (const float*)d_in[5];
    const float* bv = (const float*)d_in[6];
    const int*   src = (const int*)d_in[7];
    const int*   dst = (const int*)d_in[8];

    int nN = in_sizes[0] / IN_DIM;
    int nE = in_sizes[7];
    if (nN > N_NODES_MAX) nN = N_NODES_MAX;
    if (nE > N_EDGES_MAX) nE = N_EDGES_MAX;

    float* out = (float*)d_out;
    int nb = (nN + 1023) / 1024;

    static bool attr_done = false;
    if (!attr_done) {
        cudaFuncSetAttribute(wmma_qkv_kernel,
                             cudaFuncAttributeMaxDynamicSharedMemorySize, SM_TOTAL);
        attr_done = true;
    }

    static cudaStream_t s2 = nullptr;
    static cudaEvent_t  evF = nullptr, evJ = nullptr;
    if (!s2) {
        if (cudaStreamCreateWithFlags(&s2, cudaStreamNonBlocking) != cudaSuccess) s2 = nullptr;
        if (s2) {
            if (cudaEventCreateWithFlags(&evF, cudaEventDisableTiming) != cudaSuccess) evF = nullptr;
            if (cudaEventCreateWithFlags(&evJ, cudaEventDisableTiming) != cudaSuccess) evJ = nullptr;
        }
    }
    bool fork = (s2 && evF && evJ);

    int ggrid = (nN + 63) / 64;

    if (fork) {
        cudaEventRecord(evF, 0);
        cudaStreamWaitEvent(s2, evF, 0);

        zero_off_kernel<<<(nN + 1 + 255) / 256, 256, 0, s2>>>(nN);
        hist_kernel<<<(nE + 255) / 256, 256, 0, s2>>>(dst, nE);
        block_scan_kernel<<<nb, 1024, 0, s2>>>(nN);
        scan_add_kernel<<<nb, 1024, 0, s2>>>(nN, nb);
        scatter_kernel<<<(nE + 255) / 256, 256, 0, s2>>>(src, dst, nE);
        cudaEventRecord(evJ, s2);

        wprep_kernel<<<3, 256>>>(Wq, Wk, Wv);
        wmma_qkv_kernel<<<ggrid, 256, SM_TOTAL>>>(h, bq, bk, bv, nN);

        cudaStreamWaitEvent(0, evJ, 0);
    } else {
        zero_off_kernel<<<(nN + 1 + 255) / 256, 256>>>(nN);
        wprep_kernel<<<3, 256>>>(Wq, Wk, Wv);
        wmma_qkv_kernel<<<ggrid, 256, SM_TOTAL>>>(h, bq, bk, bv, nN);
        hist_kernel<<<(nE + 255) / 256, 256>>>(dst, nE);
        block_scan_kernel<<<nb, 1024>>>(nN);
        scan_add_kernel<<<nb, 1024>>>(nN, nb);
        scatter_kernel<<<(nE + 255) / 256, 256>>>(src, dst, nE);
    }

    int nBlocks = (nN + 7) / 8;
    consume_kernel<<<nBlocks, 256>>>(out, nN);

    (void)n_in; (void)out_size;
}